// round 2
// baseline (speedup 1.0000x reference)
#include <cuda_runtime.h>
#include <cstdint>

#define N_NODES 100000
#define D_FEAT 32

// Scratch: per-node in-degree (float so the finalize divide is direct).
__device__ float g_deg[N_NODES];

// ---------------------------------------------------------------------------
// Kernel 1: zero the output accumulator and the degree array.
// ---------------------------------------------------------------------------
__global__ void zero_kernel(float4* __restrict__ out)
{
    const int total4 = N_NODES * D_FEAT / 4;   // 800,000 float4
    int i = blockIdx.x * blockDim.x + threadIdx.x;
    int stride = gridDim.x * blockDim.x;
    for (int k = i; k < total4; k += stride)
        out[k] = make_float4(0.f, 0.f, 0.f, 0.f);
    for (int k = i; k < N_NODES; k += stride)
        g_deg[k] = 0.f;
}

// ---------------------------------------------------------------------------
// Kernel 2: edge scatter. 8 threads per edge; each thread handles one float4
// (4 features). msg = rel[src] * pattern[e]; red.add.v4 into out[dst].
// Indices are INT32 (JAX x64 disabled downcasts int64 -> int32).
// ---------------------------------------------------------------------------
__global__ void __launch_bounds__(256)
edge_kernel(const float4* __restrict__ rel,       // [N, 8] float4
            const float4* __restrict__ pat,       // [E, 8] float4
            const int* __restrict__ src,          // [E] int32
            const int* __restrict__ dst,          // [E] int32
            float* __restrict__ out,              // [N, 32]
            int n_edges)
{
    long long tid = (long long)blockIdx.x * blockDim.x + threadIdx.x;
    int lane = (int)(tid & 7);
    long long e = tid >> 3;
    if (e >= n_edges) return;

    int s = __ldg(&src[e]);
    int d = __ldg(&dst[e]);

    float4 r = __ldg(&rel[(long long)s * 8 + lane]);
    float4 p = __ldg(&pat[e * 8 + lane]);

    float mx = r.x * p.x;
    float my = r.y * p.y;
    float mz = r.z * p.z;
    float mw = r.w * p.w;

    float* dp = out + (long long)d * 32 + lane * 4;
    asm volatile("red.global.add.v4.f32 [%0], {%1, %2, %3, %4};"
                 :: "l"(dp), "f"(mx), "f"(my), "f"(mz), "f"(mw)
                 : "memory");

    if (lane == 0)
        atomicAdd(&g_deg[d], 1.0f);   // no return value used -> REDG
}

// ---------------------------------------------------------------------------
// Kernel 3: finalize. out = out / max(deg, 1) + rel.  float4 per thread.
// ---------------------------------------------------------------------------
__global__ void __launch_bounds__(256)
final_kernel(const float4* __restrict__ rel, float4* __restrict__ out)
{
    const int total4 = N_NODES * D_FEAT / 4;
    int i = blockIdx.x * blockDim.x + threadIdx.x;
    if (i >= total4) return;

    int node = i >> 3;                   // 8 float4 per node
    float inv = 1.0f / fmaxf(g_deg[node], 1.0f);

    float4 o = out[i];
    float4 r = __ldg(&rel[i]);
    o.x = fmaf(o.x, inv, r.x);
    o.y = fmaf(o.y, inv, r.y);
    o.z = fmaf(o.z, inv, r.z);
    o.w = fmaf(o.w, inv, r.w);
    out[i] = o;
}

// ---------------------------------------------------------------------------
extern "C" void kernel_launch(void* const* d_in, const int* in_sizes, int n_in,
                              void* d_out, int out_size)
{
    const float4* rel = (const float4*)d_in[0];     // [N, 32] f32
    const float4* pat = (const float4*)d_in[1];     // [E, 32] f32
    const int*    src = (const int*)d_in[2];        // [E] int32
    const int*    dst = (const int*)d_in[3];        // [E] int32
    float* out = (float*)d_out;

    const int n_edges = in_sizes[2];                // 1,600,000

    // 1) zero accumulators
    zero_kernel<<<592, 256>>>((float4*)out);

    // 2) edge scatter: 8 threads per edge
    long long total_threads = (long long)n_edges * 8;
    int blocks = (int)((total_threads + 255) / 256);
    edge_kernel<<<blocks, 256>>>(rel, pat, src, dst, out, n_edges);

    // 3) finalize
    int total4 = N_NODES * D_FEAT / 4;
    final_kernel<<<(total4 + 255) / 256, 256>>>(rel, (float4*)out);
}

// round 3
// speedup vs baseline: 1.0496x; 1.0496x over previous
#include <cuda_runtime.h>
#include <cstdint>

#define N_NODES 100000
#define CAP 64          // per-node bucket capacity; P(in-degree > 64) ~ 1e-16

// Scratch (device globals — no runtime allocation allowed).
__device__ int  g_cursor[N_NODES];                       // doubles as in-degree
__device__ int2 g_slot[(size_t)N_NODES * CAP];           // (src, edge_id) pairs, 51.2 MB

// ---------------------------------------------------------------------------
// Kernel 1: zero the per-node cursors.
// ---------------------------------------------------------------------------
__global__ void zero_cursor_kernel()
{
    int i = blockIdx.x * blockDim.x + threadIdx.x;
    if (i < N_NODES) g_cursor[i] = 0;
}

// ---------------------------------------------------------------------------
// Kernel 2: bucket fill. One thread per edge: claim a slot in dst's bucket,
// store (src, edge_id).
// ---------------------------------------------------------------------------
__global__ void __launch_bounds__(256)
fill_kernel(const int* __restrict__ src, const int* __restrict__ dst, int n_edges)
{
    int e = blockIdx.x * blockDim.x + threadIdx.x;
    if (e >= n_edges) return;
    int s = __ldg(&src[e]);
    int d = __ldg(&dst[e]);
    int pos = atomicAdd(&g_cursor[d], 1);
    if (pos < CAP)
        g_slot[(size_t)d * CAP + pos] = make_int2(s, e);
}

// ---------------------------------------------------------------------------
// Kernel 3: gather + reduce + finalize. 8 threads per node, one float4 lane
// each. No atomics; out written exactly once.
// ---------------------------------------------------------------------------
__global__ void __launch_bounds__(256)
gather_kernel(const float4* __restrict__ rel,      // [N, 8] float4
              const float4* __restrict__ pat,      // [E, 8] float4
              float4* __restrict__ out)            // [N, 8] float4
{
    int t = blockIdx.x * blockDim.x + threadIdx.x;
    int node = t >> 3;
    int lane = t & 7;
    if (node >= N_NODES) return;

    int deg = g_cursor[node];
    int n = min(deg, CAP);
    const int2* slots = &g_slot[(size_t)node * CAP];

    float4 acc = make_float4(0.f, 0.f, 0.f, 0.f);

    int i = 0;
    for (; i + 1 < n; i += 2) {
        int2 a = slots[i];
        int2 b = slots[i + 1];
        // pattern: streaming (evict-first) — protect L2 residency of rel/out.
        float4 p0 = __ldcs(&pat[(size_t)a.y * 8 + lane]);
        float4 r0 = __ldg (&rel[(size_t)a.x * 8 + lane]);
        float4 p1 = __ldcs(&pat[(size_t)b.y * 8 + lane]);
        float4 r1 = __ldg (&rel[(size_t)b.x * 8 + lane]);
        acc.x = fmaf(r0.x, p0.x, acc.x);
        acc.y = fmaf(r0.y, p0.y, acc.y);
        acc.z = fmaf(r0.z, p0.z, acc.z);
        acc.w = fmaf(r0.w, p0.w, acc.w);
        acc.x = fmaf(r1.x, p1.x, acc.x);
        acc.y = fmaf(r1.y, p1.y, acc.y);
        acc.z = fmaf(r1.z, p1.z, acc.z);
        acc.w = fmaf(r1.w, p1.w, acc.w);
    }
    if (i < n) {
        int2 a = slots[i];
        float4 p0 = __ldcs(&pat[(size_t)a.y * 8 + lane]);
        float4 r0 = __ldg (&rel[(size_t)a.x * 8 + lane]);
        acc.x = fmaf(r0.x, p0.x, acc.x);
        acc.y = fmaf(r0.y, p0.y, acc.y);
        acc.z = fmaf(r0.z, p0.z, acc.z);
        acc.w = fmaf(r0.w, p0.w, acc.w);
    }

    float inv = 1.0f / fmaxf((float)deg, 1.0f);
    float4 rl = __ldg(&rel[node * 8 + lane]);
    float4 o;
    o.x = fmaf(acc.x, inv, rl.x);
    o.y = fmaf(acc.y, inv, rl.y);
    o.z = fmaf(acc.z, inv, rl.z);
    o.w = fmaf(acc.w, inv, rl.w);
    out[node * 8 + lane] = o;
}

// ---------------------------------------------------------------------------
extern "C" void kernel_launch(void* const* d_in, const int* in_sizes, int n_in,
                              void* d_out, int out_size)
{
    const float4* rel = (const float4*)d_in[0];     // [N, 32] f32
    const float4* pat = (const float4*)d_in[1];     // [E, 32] f32
    const int*    src = (const int*)d_in[2];        // [E] int32
    const int*    dst = (const int*)d_in[3];        // [E] int32
    float4* out = (float4*)d_out;

    const int n_edges = in_sizes[2];                // 1,600,000

    // 1) zero bucket cursors
    zero_cursor_kernel<<<(N_NODES + 1023) / 1024, 1024>>>();

    // 2) bucket fill (scatter of (src, eid) pairs)
    fill_kernel<<<(n_edges + 255) / 256, 256>>>(src, dst, n_edges);

    // 3) gather + mean + residual add
    int total_threads = N_NODES * 8;
    gather_kernel<<<(total_threads + 255) / 256, 256>>>(rel, pat, out);
}